// round 11
// baseline (speedup 1.0000x reference)
#include <cuda_runtime.h>
#include <cuda_fp16.h>
#include <math.h>

// ---------------------------------------------------------------------------
// GlobalMHSAWithPosBias: B=128, C=512, RES=14 (N=196), HEADS=8, hd=64
// Round 11: 3-stage cp.async GEMM pipeline (1 barrier/iter); Q/K written in
// d-pair half2 layout by the QKV epilogue (shfl-based) so attention staging
// is pure coalesced 4B loads.
// NOTE: never pass __device__ symbols from host code (rounds-3/4 bug).
// ---------------------------------------------------------------------------

#define B_    128
#define CIN   512
#define NQ    196
#define NPAD  224          // 4 * 56 = 2 * 112
#define HEADS 8
#define HD    64
#define EPS_  1e-5f

// fp16 operand layouts:
//  g_wh: uint2[pr][256 kp], pr = base + (o>>4)*8 + (o&7); .x=h2 W[o], .y=h2 W[o+8]
//  g_xh/g_att: half2 pairs, idx = ((b*128+sb)*224+n)*2 + hi,
//    sb=(kp>>3)*4+(kp&3), hi=(kp>>2)&1, halves by (c&1)
//  g_qkP: unsigned[b][512][224]; row c>>1 (c<1024: Q then K), word m = h2(c, c+1)
//  g_vh : half[b][512][224]; row c-1024 (V), halves along n
__device__ unsigned g_wh [(size_t)1024 * 256 * 2];
__device__ unsigned g_xh [(size_t)B_ * 128 * NPAD * 2];     // BSS 0 (pad cols)
__device__ unsigned g_att[(size_t)B_ * 128 * NPAD * 2];     // BSS 0
__device__ unsigned g_qkP[(size_t)B_ * 512 * NPAD];
__device__ unsigned short g_vh[(size_t)B_ * 512 * NPAD];
__device__ float    g_biasT[HEADS * NQ * NQ];

// ---------------------------------------------------------------------------
__device__ __forceinline__ void mma_f16(float c[4], const unsigned a[4],
                                        unsigned b0, unsigned b1) {
    asm volatile(
        "mma.sync.aligned.m16n8k16.row.col.f32.f16.f16.f32 "
        "{%0,%1,%2,%3}, {%4,%5,%6,%7}, {%8,%9}, {%0,%1,%2,%3};\n"
        : "+f"(c[0]), "+f"(c[1]), "+f"(c[2]), "+f"(c[3])
        : "r"(a[0]), "r"(a[1]), "r"(a[2]), "r"(a[3]), "r"(b0), "r"(b1));
}

__device__ __forceinline__ void cp16(void* dst, const void* src) {
    unsigned s = (unsigned)__cvta_generic_to_shared(dst);
    asm volatile("cp.async.cg.shared.global [%0], [%1], 16;" :: "r"(s), "l"(src));
}
__device__ __forceinline__ void cp_commit() {
    asm volatile("cp.async.commit_group;");
}
template <int N>
__device__ __forceinline__ void cp_wait() {
    asm volatile("cp.async.wait_group %0;" :: "n"(N));
}

__device__ __forceinline__ unsigned packh2(float lo, float hi) {
    __half2 h = __floats2half2_rn(lo, hi);
    return *(unsigned*)&h;
}

// ---------------------------------------------------------------------------
// prologue converters
// ---------------------------------------------------------------------------
__global__ void cvt_w_kernel(const float* __restrict__ qkv_w,
                             const float* __restrict__ proj_w) {
    int i = blockIdx.x * blockDim.x + threadIdx.x;
    const int n1 = 3 * CIN * CIN, total = n1 + CIN * CIN;
    if (i >= total) return;
    float v;
    int o, k, basepr;
    if (i < n1) { v = qkv_w[i];       o = i / CIN;        k = i % CIN;        basepr = 0; }
    else        { v = proj_w[i - n1]; o = (i - n1) / CIN; k = (i - n1) % CIN; basepr = 768; }
    int pr   = basepr + (o >> 4) * 8 + (o & 7);
    int comp = (o >> 3) & 1;
    int kp   = k >> 1;
    ((__half*)g_wh)[(size_t)pr * 1024 + kp * 4 + comp * 2 + (k & 1)]
        = __float2half_rn(v);
}

__global__ void pad_cvt_x_kernel(const float* __restrict__ x) {
    int i = blockIdx.x * blockDim.x + threadIdx.x;
    const int total = B_ * 128 * NPAD * 2;
    if (i >= total) return;
    int hi = i & 1;
    int n  = (i >> 1) % NPAD;
    int r  = (i >> 1) / NPAD;          // b*128 + sb
    if (n >= NQ) return;               // pad cols stay 0 (BSS)
    int b  = r >> 7, sb = r & 127;
    int kp = (sb >> 2) * 8 + hi * 4 + (sb & 3);
    int c  = kp * 2;
    const float* xp = x + ((size_t)b * CIN + c) * NQ + n;
    g_xh[((size_t)r * NPAD + n) * 2 + hi] = packh2(xp[0], xp[NQ]);
}

__global__ void gather_bias_kernel(const float* __restrict__ ab,
                                   const int*   __restrict__ idxs) {
    int i = blockIdx.x * blockDim.x + threadIdx.x;
    const int total = HEADS * NQ * NQ;
    if (i >= total) return;
    int stride = (idxs[1] == 0 && idxs[3] == 0) ? 2 : 1;   // int64 detection
    int h = i / (NQ * NQ);
    int j = i - h * (NQ * NQ);
    g_biasT[i] = ab[h * NQ + idxs[(size_t)j * stride]];
}

// ---------------------------------------------------------------------------
// fp16 GEMM + fused BN affine; pair-packed operands, 3-stage cp.async, BK=64.
// MODE 0: X=g_xh,  W pr base 0,   Y = g_qkP (o<1024, shfl pair-pack) / g_vh
// MODE 1: X=g_att, W pr base 768, Y = outp (f32, ldy=196, guarded)
// BM=128, BN=112, BK=64, 256 threads (8 warps, 4m x 2n), warp tile 32x56.
// ---------------------------------------------------------------------------
#define WP2 36
#define XP2 116
#define WS_T2 (64 * WP2)
#define XS_T2 (16 * XP2)
#define ST_SZ (WS_T2 + XS_T2)

template <int MODE>
__global__ __launch_bounds__(256)
void gemm_f16(const float* __restrict__ gamma, const float* __restrict__ beta,
              const float* __restrict__ mean,  const float* __restrict__ var,
              float* __restrict__ outp) {
    extern __shared__ uint2 smg[];      // 3 stages of [W | X]

    const uint2* __restrict__ X2 = (MODE == 0) ? (const uint2*)g_xh
                                               : (const uint2*)g_att;
    const uint2* __restrict__ W2 = (const uint2*)g_wh
                                   + (MODE == 0 ? 0 : (size_t)768 * 256);
    const int Ocnt = (MODE == 0) ? 3 * CIN : CIN;

    const int tid  = threadIdx.x;
    const int lane = tid & 31;
    const int wid  = tid >> 5;
    const int wm   = wid & 3;
    const int n0w  = (wid >> 2) * 56;

    const int b  = blockIdx.z;
    const int o0 = blockIdx.y * 128;
    const int n0 = blockIdx.x * 112;

    const uint2* __restrict__ Wp = W2 + (size_t)(o0 / 2) * 256;
    const uint2* __restrict__ Xp = X2 + ((size_t)b * 128) * NPAD + n0;

    float acc[2][7][4];
#pragma unroll
    for (int i = 0; i < 2; i++)
#pragma unroll
        for (int j = 0; j < 7; j++)
#pragma unroll
            for (int k = 0; k < 4; k++) acc[i][j][k] = 0.f;

    const int row = lane >> 2;
    const int col = lane & 3;

    auto load_tiles = [&](int it, int st) {
        uint2* ws = smg + st * ST_SZ;
        uint2* xs = ws + WS_T2;
#pragma unroll
        for (int i = tid; i < 1024; i += 256) {
            int r = i >> 4, c2 = (i & 15) * 2;
            cp16(ws + r * WP2 + c2, Wp + (size_t)r * 256 + it * 32 + c2);
        }
#pragma unroll
        for (int i = tid; i < 896; i += 256) {
            int r = i / 56, c2 = (i % 56) * 2;
            cp16(xs + r * XP2 + c2, Xp + (size_t)(it * 16 + r) * NPAD + c2);
        }
        cp_commit();
    };

    load_tiles(0, 0);
    load_tiles(1, 1);

    for (int it = 0; it < 8; ++it) {
        if (it < 6) cp_wait<1>(); else cp_wait<0>();
        __syncthreads();

        const uint2* ws = smg + (it % 3) * ST_SZ;
        const uint2* xs = ws + WS_T2;
#pragma unroll
        for (int ks = 0; ks < 4; ks++) {
            unsigned a[2][4];
#pragma unroll
            for (int mt = 0; mt < 2; mt++) {
                int pr = (wm * 2 + mt) * 8 + row;
                uint2 A01 = ws[pr * WP2 + ks * 8 + col];
                uint2 A23 = ws[pr * WP2 + ks * 8 + col + 4];
                a[mt][0] = A01.x; a[mt][1] = A01.y;
                a[mt][2] = A23.x; a[mt][3] = A23.y;
            }
#pragma unroll
            for (int nt = 0; nt < 7; nt++) {
                uint2 Bf = xs[(ks * 4 + col) * XP2 + n0w + nt * 8 + row];
                mma_f16(acc[0][nt], a[0], Bf.x, Bf.y);
                mma_f16(acc[1][nt], a[1], Bf.x, Bf.y);
            }
        }
        if (it + 2 < 8) load_tiles(it + 2, (it + 2) % 3);
    }

    // epilogue: BN affine + store
    const bool qk = (MODE == 0) && (o0 < 1024);
#pragma unroll
    for (int mt = 0; mt < 2; mt++) {
        int o_a = o0 + wm * 32 + mt * 16 + row;
        int o_b = o_a + 8;
        float inv_a = gamma[o_a] * rsqrtf(var[o_a] + EPS_);
        float sh_a  = beta[o_a] - mean[o_a] * inv_a;
        float inv_b = gamma[o_b] * rsqrtf(var[o_b] + EPS_);
        float sh_b  = beta[o_b] - mean[o_b] * inv_b;
#pragma unroll
        for (int nt = 0; nt < 7; nt++) {
            int c0 = n0 + n0w + nt * 8 + col * 2;
            float y0 = acc[mt][nt][0] * inv_a + sh_a;
            float y1 = acc[mt][nt][1] * inv_a + sh_a;
            float y2 = acc[mt][nt][2] * inv_b + sh_b;
            float y3 = acc[mt][nt][3] * inv_b + sh_b;
            if (MODE == 0) {
                if (qk) {
                    // pair channel o with o+1 (held by lane+4: row+1)
                    float z0 = __shfl_down_sync(0xffffffffu, y0, 4);
                    float z1 = __shfl_down_sync(0xffffffffu, y1, 4);
                    float z2 = __shfl_down_sync(0xffffffffu, y2, 4);
                    float z3 = __shfl_down_sync(0xffffffffu, y3, 4);
                    if (!(row & 1)) {
                        int prA = o_a >> 1;               // [0,512)
                        int prB = prA + 4;
                        uint2 wa = make_uint2(packh2(y0, z0), packh2(y1, z1));
                        uint2 wb = make_uint2(packh2(y2, z2), packh2(y3, z3));
                        *(uint2*)(g_qkP + ((size_t)b * 512 + prA) * NPAD + c0) = wa;
                        *(uint2*)(g_qkP + ((size_t)b * 512 + prB) * NPAD + c0) = wb;
                    }
                } else {
                    int ca = o_a - 1024, cb = o_b - 1024;
                    *(unsigned*)(g_vh + ((size_t)b * 512 + ca) * NPAD + c0)
                        = packh2(y0, y1);
                    *(unsigned*)(g_vh + ((size_t)b * 512 + cb) * NPAD + c0)
                        = packh2(y2, y3);
                }
            } else {
                float* ya = outp + ((size_t)b * Ocnt + o_a) * NQ;
                float* yb = outp + ((size_t)b * Ocnt + o_b) * NQ;
                if (c0 < NQ)     { ya[c0]     = y0; yb[c0]     = y2; }
                if (c0 + 1 < NQ) { ya[c0 + 1] = y1; yb[c0 + 1] = y3; }
            }
        }
    }
}

// ---------------------------------------------------------------------------
// fp16 tensor-core attention (round-10 core). Staging now reads g_qkP/g_vh
// with coalesced 4B loads. One block per (b,h): 448 threads, 2 blocks/SM.
// ---------------------------------------------------------------------------
#define KP2 232
#define VP2 72
#define PP2 20
#define AQS_O 0
#define AKS_O (32 * KP2)
#define AVS_O (2 * 32 * KP2)
#define APT_O (AVS_O + 112 * VP2)
#define ASM_WORDS (APT_O + 14 * 16 * PP2)

__global__ __launch_bounds__(448, 2)
void attn_kernel() {
    extern __shared__ unsigned sm[];
    unsigned* Qs = sm + AQS_O;
    unsigned* Ks = sm + AKS_O;
    unsigned* Vs = sm + AVS_O;
    unsigned* Pt = sm + APT_O;

    const int tid  = threadIdx.x;
    const int lane = tid & 31;
    const int w    = tid >> 5;          // 0..13
    const int row  = lane >> 2;         // 0..7
    const int col  = lane & 3;          // 0..3
    const int b    = blockIdx.x >> 3;
    const int h    = blockIdx.x & 7;
    const int n0   = w * 16;

    // stage Q,K from d-pair layout (coalesced 4B loads)
    const unsigned* __restrict__ qsrc = g_qkP + ((size_t)b * 512 + h * 32) * NPAD;
    const unsigned* __restrict__ ksrc = g_qkP + ((size_t)b * 512 + 256 + h * 32) * NPAD;
    for (int i = tid; i < 32 * NPAD; i += 448) {
        int dp = i / NPAD, m = i - dp * NPAD;
        Qs[dp * KP2 + m] = qsrc[(size_t)dp * NPAD + m];
        Ks[dp * KP2 + m] = ksrc[(size_t)dp * NPAD + m];
    }
    // stage V^T [mp][d] (4B loads along n)
    const unsigned short* __restrict__ vsrc = g_vh + ((size_t)b * 512 + h * 64) * NPAD;
    for (int i = tid; i < 64 * 112; i += 448) {
        int d = i / 112, mp = i - d * 112;
        Vs[mp * VP2 + d] = *(const unsigned*)(vsrc + (size_t)d * NPAD + 2 * mp);
    }
    __syncthreads();

    const float* __restrict__ bptr = g_biasT + (size_t)h * NQ * NQ;
    unsigned* ptw = Pt + w * 16 * PP2;
    const int nb_lo = min(n0 + row, NQ - 1);
    const int nb_hi = min(n0 + row + 8, NQ - 1);

    float o[8][4];
#pragma unroll
    for (int i = 0; i < 8; i++)
#pragma unroll
        for (int j = 0; j < 4; j++) o[i][j] = 0.f;
    float ll = 0.f, lh = 0.f;

    for (int mc = 0; mc < 7; mc++) {
        const int m0 = mc * 32;

        // ---- S = Q^T K for columns [m0, m0+32): 4 k16-steps over d ----
        float c[4][4];
#pragma unroll
        for (int s = 0; s < 4; s++)
#pragma unroll
            for (int j = 0; j < 4; j++) c[s][j] = 0.f;

#pragma unroll
        for (int t = 0; t < 4; t++) {
            const int qb = (t * 8 + col) * KP2 + n0 + row;
            unsigned a[4];
            a[0] = Qs[qb];
            a[1] = Qs[qb + 8];
            a[2] = Qs[qb + 4 * KP2];
            a[3] = Qs[qb + 4 * KP2 + 8];
#pragma unroll
            for (int s = 0; s < 4; s++) {
                const int kb = (t * 8 + col) * KP2 + m0 + s * 8 + row;
                mma_f16(c[s], a, Ks[kb], Ks[kb + 4 * KP2]);
            }
        }

        // exp + bias -> Pt (half2 pairs along m)
#pragma unroll
        for (int s = 0; s < 4; s++) {
            const int m_b = m0 + s * 8 + 2 * col;
            float p0 = 0.f, p1 = 0.f, p2 = 0.f, p3 = 0.f;
            if (m_b < NQ) {
                float2 blo = *(const float2*)(bptr + (size_t)nb_lo * NQ + m_b);
                float2 bhi = *(const float2*)(bptr + (size_t)nb_hi * NQ + m_b);
                p0 = __expf(c[s][0] * 0.125f + blo.x);
                p1 = __expf(c[s][1] * 0.125f + blo.y);
                p2 = __expf(c[s][2] * 0.125f + bhi.x);
                p3 = __expf(c[s][3] * 0.125f + bhi.y);
            }
            ll += p0 + p1;
            lh += p2 + p3;
            ptw[row * PP2 + s * 4 + col]       = packh2(p0, p1);
            ptw[(row + 8) * PP2 + s * 4 + col] = packh2(p2, p3);
        }
        __syncwarp();

        // ---- O += P V^T: 2 k16-steps over this m-chunk ----
#pragma unroll
        for (int u = 0; u < 2; u++) {
            unsigned a[4];
            a[0] = ptw[row * PP2 + u * 8 + col];
            a[1] = ptw[(row + 8) * PP2 + u * 8 + col];
            a[2] = ptw[row * PP2 + u * 8 + col + 4];
            a[3] = ptw[(row + 8) * PP2 + u * 8 + col + 4];
#pragma unroll
            for (int nc = 0; nc < 8; nc++) {
                const int vb = (mc * 16 + u * 8 + col) * VP2 + nc * 8 + row;
                mma_f16(o[nc], a, Vs[vb], Vs[vb + 4 * VP2]);
            }
        }
        __syncwarp();
    }

    // row sums across the quad
    ll += __shfl_xor_sync(0xffffffffu, ll, 1);
    ll += __shfl_xor_sync(0xffffffffu, ll, 2);
    lh += __shfl_xor_sync(0xffffffffu, lh, 1);
    lh += __shfl_xor_sync(0xffffffffu, lh, 2);
    const float linv_lo = 1.f / ll;
    const float linv_hi = 1.f / lh;

    __half* ap = (__half*)g_att;
    const int n_lo = n0 + row;
    const int n_hi = n0 + row + 8;
#pragma unroll
    for (int nc = 0; nc < 8; nc++) {
        int d0 = nc * 8 + 2 * col;
#pragma unroll
        for (int j = 0; j < 2; j++) {
            int d = d0 + j;
            if (n_lo < NQ) {
                float v = o[nc][j] * linv_lo;
                float gl = 0.5f * v * (1.f + erff(v * 0.70710678118654752f));
                int flat = h * (NQ * HD) + n_lo * HD + d;
                int cc   = flat / NQ;
                int pos  = flat - cc * NQ;
                int kp   = cc >> 1;
                int sb   = (kp >> 3) * 4 + (kp & 3);
                int hi   = (kp >> 2) & 1;
                ap[(((size_t)b * 128 + sb) * NPAD + pos) * 4 + hi * 2 + (cc & 1)]
                    = __float2half_rn(gl);
            }
            if (n_hi < NQ) {
                float v = o[nc][j + 2] * linv_hi;
                float gl = 0.5f * v * (1.f + erff(v * 0.70710678118654752f));
                int flat = h * (NQ * HD) + n_hi * HD + d;
                int cc   = flat / NQ;
                int pos  = flat - cc * NQ;
                int kp   = cc >> 1;
                int sb   = (kp >> 3) * 4 + (kp & 3);
                int hi   = (kp >> 2) & 1;
                ap[(((size_t)b * 128 + sb) * NPAD + pos) * 4 + hi * 2 + (cc & 1)]
                    = __float2half_rn(gl);
            }
        }
    }
}

// ---------------------------------------------------------------------------
extern "C" void kernel_launch(void* const* d_in, const int* in_sizes, int n_in,
                              void* d_out, int out_size) {
    const float* x      = (const float*)d_in[0];
    const float* qkv_w  = (const float*)d_in[1];
    const float* bn1_g  = (const float*)d_in[2];
    const float* bn1_b  = (const float*)d_in[3];
    const float* bn1_m  = (const float*)d_in[4];
    const float* bn1_v  = (const float*)d_in[5];
    const float* proj_w = (const float*)d_in[6];
    const float* bn2_g  = (const float*)d_in[7];
    const float* bn2_b  = (const float*)d_in[8];
    const float* bn2_m  = (const float*)d_in[9];
    const float* bn2_v  = (const float*)d_in[10];
    const float* ab     = (const float*)d_in[11];
    const int*   idxs   = (const int*)d_in[12];
    float* out = (float*)d_out;

    const int smem_gemm = 3 * ST_SZ * 8;                 // 99840 B
    const int smem_attn = ASM_WORDS * 4;                 // 109568 B
    cudaFuncSetAttribute(gemm_f16<0>,
                         cudaFuncAttributeMaxDynamicSharedMemorySize, smem_gemm);
    cudaFuncSetAttribute(gemm_f16<1>,
                         cudaFuncAttributeMaxDynamicSharedMemorySize, smem_gemm);
    cudaFuncSetAttribute(attn_kernel,
                         cudaFuncAttributeMaxDynamicSharedMemorySize, smem_attn);

    {   // convert weights to fp16 pair layout
        int total = 4 * CIN * CIN;
        cvt_w_kernel<<<(total + 255) / 256, 256>>>(qkv_w, proj_w);
    }
    {   // pad + convert x to fp16 pair layout (coalesced)
        int total = B_ * 128 * NPAD * 2;
        pad_cvt_x_kernel<<<(total + 255) / 256, 256>>>(x);
    }
    {   // bias gather
        int total = HEADS * NQ * NQ;
        gather_bias_kernel<<<(total + 255) / 256, 256>>>(ab, idxs);
    }
    {   // QKV GEMM + BN1 -> g_qkP (Q,K pairs) / g_vh (V rows)
        dim3 grid(NPAD / 112, (3 * CIN) / 128, B_);
        gemm_f16<0><<<grid, 256, smem_gemm>>>(bn1_g, bn1_b, bn1_m, bn1_v, nullptr);
    }
    {   // attention + gelu + scrambled reshape
        attn_kernel<<<B_ * HEADS, 448, smem_attn>>>();
    }
    {   // proj GEMM + BN2 -> d_out
        dim3 grid(NPAD / 112, CIN / 128, B_);
        gemm_f16<1><<<grid, 256, smem_gemm>>>(bn2_g, bn2_b, bn2_m, bn2_v, out);
    }
}

// round 12
// speedup vs baseline: 1.0164x; 1.0164x over previous
#include <cuda_runtime.h>
#include <cuda_fp16.h>
#include <math.h>

// ---------------------------------------------------------------------------
// GlobalMHSAWithPosBias: B=128, C=512, RES=14 (N=196), HEADS=8, hd=64
// Round 12: round-10 2-stage GEMM pipeline (the 3-stage was a regression),
// keep round-11 d-pair epilogue + coalesced attn staging, and cap GEMM regs
// with __launch_bounds__(256,3) for 3 blocks/SM.
// NOTE: never pass __device__ symbols from host code (rounds-3/4 bug).
// ---------------------------------------------------------------------------

#define B_    128
#define CIN   512
#define NQ    196
#define NPAD  224          // 4 * 56 = 2 * 112
#define HEADS 8
#define HD    64
#define EPS_  1e-5f

// fp16 operand layouts:
//  g_wh: uint2[pr][256 kp], pr = base + (o>>4)*8 + (o&7); .x=h2 W[o], .y=h2 W[o+8]
//  g_xh/g_att: half2 pairs, idx = ((b*128+sb)*224+n)*2 + hi,
//    sb=(kp>>3)*4+(kp&3), hi=(kp>>2)&1, halves by (c&1)
//  g_qkP: unsigned[b][512][224]; row c>>1 (c<1024: Q then K), word m = h2(c, c+1)
//  g_vh : half[b][512][224]; row c-1024 (V), halves along n
__device__ unsigned g_wh [(size_t)1024 * 256 * 2];
__device__ unsigned g_xh [(size_t)B_ * 128 * NPAD * 2];     // BSS 0 (pad cols)
__device__ unsigned g_att[(size_t)B_ * 128 * NPAD * 2];     // BSS 0
__device__ unsigned g_qkP[(size_t)B_ * 512 * NPAD];
__device__ unsigned short g_vh[(size_t)B_ * 512 * NPAD];
__device__ float    g_biasT[HEADS * NQ * NQ];

// ---------------------------------------------------------------------------
__device__ __forceinline__ void mma_f16(float c[4], const unsigned a[4],
                                        unsigned b0, unsigned b1) {
    asm volatile(
        "mma.sync.aligned.m16n8k16.row.col.f32.f16.f16.f32 "
        "{%0,%1,%2,%3}, {%4,%5,%6,%7}, {%8,%9}, {%0,%1,%2,%3};\n"
        : "+f"(c[0]), "+f"(c[1]), "+f"(c[2]), "+f"(c[3])
        : "r"(a[0]), "r"(a[1]), "r"(a[2]), "r"(a[3]), "r"(b0), "r"(b1));
}

__device__ __forceinline__ void cp16(void* dst, const void* src) {
    unsigned s = (unsigned)__cvta_generic_to_shared(dst);
    asm volatile("cp.async.cg.shared.global [%0], [%1], 16;" :: "r"(s), "l"(src));
}
__device__ __forceinline__ void cp_commit() {
    asm volatile("cp.async.commit_group;");
}
template <int N>
__device__ __forceinline__ void cp_wait() {
    asm volatile("cp.async.wait_group %0;" :: "n"(N));
}

__device__ __forceinline__ unsigned packh2(float lo, float hi) {
    __half2 h = __floats2half2_rn(lo, hi);
    return *(unsigned*)&h;
}

// ---------------------------------------------------------------------------
// prologue converters
// ---------------------------------------------------------------------------
__global__ void cvt_w_kernel(const float* __restrict__ qkv_w,
                             const float* __restrict__ proj_w) {
    int i = blockIdx.x * blockDim.x + threadIdx.x;
    const int n1 = 3 * CIN * CIN, total = n1 + CIN * CIN;
    if (i >= total) return;
    float v;
    int o, k, basepr;
    if (i < n1) { v = qkv_w[i];       o = i / CIN;        k = i % CIN;        basepr = 0; }
    else        { v = proj_w[i - n1]; o = (i - n1) / CIN; k = (i - n1) % CIN; basepr = 768; }
    int pr   = basepr + (o >> 4) * 8 + (o & 7);
    int comp = (o >> 3) & 1;
    int kp   = k >> 1;
    ((__half*)g_wh)[(size_t)pr * 1024 + kp * 4 + comp * 2 + (k & 1)]
        = __float2half_rn(v);
}

__global__ void pad_cvt_x_kernel(const float* __restrict__ x) {
    int i = blockIdx.x * blockDim.x + threadIdx.x;
    const int total = B_ * 128 * NPAD * 2;
    if (i >= total) return;
    int hi = i & 1;
    int n  = (i >> 1) % NPAD;
    int r  = (i >> 1) / NPAD;          // b*128 + sb
    if (n >= NQ) return;               // pad cols stay 0 (BSS)
    int b  = r >> 7, sb = r & 127;
    int kp = (sb >> 2) * 8 + hi * 4 + (sb & 3);
    int c  = kp * 2;
    const float* xp = x + ((size_t)b * CIN + c) * NQ + n;
    g_xh[((size_t)r * NPAD + n) * 2 + hi] = packh2(xp[0], xp[NQ]);
}

__global__ void gather_bias_kernel(const float* __restrict__ ab,
                                   const int*   __restrict__ idxs) {
    int i = blockIdx.x * blockDim.x + threadIdx.x;
    const int total = HEADS * NQ * NQ;
    if (i >= total) return;
    int stride = (idxs[1] == 0 && idxs[3] == 0) ? 2 : 1;   // int64 detection
    int h = i / (NQ * NQ);
    int j = i - h * (NQ * NQ);
    g_biasT[i] = ab[h * NQ + idxs[(size_t)j * stride]];
}

// ---------------------------------------------------------------------------
// fp16 GEMM + fused BN affine; pair-packed operands, 2-stage cp.async, BK=64.
// MODE 0: X=g_xh,  W pr base 0,   Y = g_qkP (o<1024, shfl pair-pack) / g_vh
// MODE 1: X=g_att, W pr base 768, Y = outp (f32, ldy=196, guarded)
// BM=128, BN=112, BK=64, 256 threads (8 warps, 4m x 2n), warp tile 32x56.
// launch_bounds(256,3): reg cap 85 -> 3 blocks/SM (smem 3x66.5KB = 199KB ok).
// ---------------------------------------------------------------------------
#define WP2 36
#define XP2 116
#define WS_T2 (64 * WP2)
#define XS_T2 (16 * XP2)

template <int MODE>
__global__ __launch_bounds__(256, 3)
void gemm_f16(const float* __restrict__ gamma, const float* __restrict__ beta,
              const float* __restrict__ mean,  const float* __restrict__ var,
              float* __restrict__ outp) {
    extern __shared__ uint2 smg[];
    uint2* Ws = smg;                  // 2 stages
    uint2* Xs = smg + 2 * WS_T2;      // 2 stages

    const uint2* __restrict__ X2 = (MODE == 0) ? (const uint2*)g_xh
                                               : (const uint2*)g_att;
    const uint2* __restrict__ W2 = (const uint2*)g_wh
                                   + (MODE == 0 ? 0 : (size_t)768 * 256);
    const int Ocnt = (MODE == 0) ? 3 * CIN : CIN;

    const int tid  = threadIdx.x;
    const int lane = tid & 31;
    const int wid  = tid >> 5;
    const int wm   = wid & 3;
    const int n0w  = (wid >> 2) * 56;

    const int b  = blockIdx.z;
    const int o0 = blockIdx.y * 128;
    const int n0 = blockIdx.x * 112;

    const uint2* __restrict__ Wp = W2 + (size_t)(o0 / 2) * 256;
    const uint2* __restrict__ Xp = X2 + ((size_t)b * 128) * NPAD + n0;

    float acc[2][7][4];
#pragma unroll
    for (int i = 0; i < 2; i++)
#pragma unroll
        for (int j = 0; j < 7; j++)
#pragma unroll
            for (int k = 0; k < 4; k++) acc[i][j][k] = 0.f;

    const int row = lane >> 2;
    const int col = lane & 3;

    auto load_tiles = [&](int it, int st) {
        uint2* ws = Ws + st * WS_T2;
        uint2* xs = Xs + st * XS_T2;
#pragma unroll
        for (int i = tid; i < 1024; i += 256) {
            int r = i >> 4, c2 = (i & 15) * 2;
            cp16(ws + r * WP2 + c2, Wp + (size_t)r * 256 + it * 32 + c2);
        }
#pragma unroll
        for (int i = tid; i < 896; i += 256) {
            int r = i / 56, c2 = (i % 56) * 2;
            cp16(xs + r * XP2 + c2, Xp + (size_t)(it * 16 + r) * NPAD + c2);
        }
        cp_commit();
    };

    load_tiles(0, 0);

    for (int it = 0; it < 8; ++it) {
        const int cur = it & 1;
        if (it + 1 < 8) {
            load_tiles(it + 1, (it + 1) & 1);
            cp_wait<1>();
        } else {
            cp_wait<0>();
        }
        __syncthreads();

        const uint2* ws = Ws + cur * WS_T2;
        const uint2* xs = Xs + cur * XS_T2;
#pragma unroll
        for (int ks = 0; ks < 4; ks++) {
            unsigned a[2][4];
#pragma unroll
            for (int mt = 0; mt < 2; mt++) {
                int pr = (wm * 2 + mt) * 8 + row;
                uint2 A01 = ws[pr * WP2 + ks * 8 + col];
                uint2 A23 = ws[pr * WP2 + ks * 8 + col + 4];
                a[mt][0] = A01.x; a[mt][1] = A01.y;
                a[mt][2] = A23.x; a[mt][3] = A23.y;
            }
#pragma unroll
            for (int nt = 0; nt < 7; nt++) {
                uint2 Bf = xs[(ks * 4 + col) * XP2 + n0w + nt * 8 + row];
                mma_f16(acc[0][nt], a[0], Bf.x, Bf.y);
                mma_f16(acc[1][nt], a[1], Bf.x, Bf.y);
            }
        }
        __syncthreads();
    }

    // epilogue: BN affine + store
    const bool qk = (MODE == 0) && (o0 < 1024);
#pragma unroll
    for (int mt = 0; mt < 2; mt++) {
        int o_a = o0 + wm * 32 + mt * 16 + row;
        int o_b = o_a + 8;
        float inv_a = gamma[o_a] * rsqrtf(var[o_a] + EPS_);
        float sh_a  = beta[o_a] - mean[o_a] * inv_a;
        float inv_b = gamma[o_b] * rsqrtf(var[o_b] + EPS_);
        float sh_b  = beta[o_b] - mean[o_b] * inv_b;
#pragma unroll
        for (int nt = 0; nt < 7; nt++) {
            int c0 = n0 + n0w + nt * 8 + col * 2;
            float y0 = acc[mt][nt][0] * inv_a + sh_a;
            float y1 = acc[mt][nt][1] * inv_a + sh_a;
            float y2 = acc[mt][nt][2] * inv_b + sh_b;
            float y3 = acc[mt][nt][3] * inv_b + sh_b;
            if (MODE == 0) {
                if (qk) {
                    // pair channel o with o+1 (held by lane+4: row+1)
                    float z0 = __shfl_down_sync(0xffffffffu, y0, 4);
                    float z1 = __shfl_down_sync(0xffffffffu, y1, 4);
                    float z2 = __shfl_down_sync(0xffffffffu, y2, 4);
                    float z3 = __shfl_down_sync(0xffffffffu, y3, 4);
                    if (!(row & 1)) {
                        int prA = o_a >> 1;               // [0,512)
                        int prB = prA + 4;
                        uint2 wa = make_uint2(packh2(y0, z0), packh2(y1, z1));
                        uint2 wb = make_uint2(packh2(y2, z2), packh2(y3, z3));
                        *(uint2*)(g_qkP + ((size_t)b * 512 + prA) * NPAD + c0) = wa;
                        *(uint2*)(g_qkP + ((size_t)b * 512 + prB) * NPAD + c0) = wb;
                    }
                } else {
                    int ca = o_a - 1024, cb = o_b - 1024;
                    *(unsigned*)(g_vh + ((size_t)b * 512 + ca) * NPAD + c0)
                        = packh2(y0, y1);
                    *(unsigned*)(g_vh + ((size_t)b * 512 + cb) * NPAD + c0)
                        = packh2(y2, y3);
                }
            } else {
                float* ya = outp + ((size_t)b * Ocnt + o_a) * NQ;
                float* yb = outp + ((size_t)b * Ocnt + o_b) * NQ;
                if (c0 < NQ)     { ya[c0]     = y0; yb[c0]     = y2; }
                if (c0 + 1 < NQ) { ya[c0 + 1] = y1; yb[c0 + 1] = y3; }
            }
        }
    }
}

// ---------------------------------------------------------------------------
// fp16 tensor-core attention. Staging reads g_qkP/g_vh with coalesced 4B
// loads. One block per (b,h): 448 threads = 14 warps, 2 blocks/SM.
// ---------------------------------------------------------------------------
#define KP2 232
#define VP2 72
#define PP2 20
#define AQS_O 0
#define AKS_O (32 * KP2)
#define AVS_O (2 * 32 * KP2)
#define APT_O (AVS_O + 112 * VP2)
#define ASM_WORDS (APT_O + 14 * 16 * PP2)

__global__ __launch_bounds__(448, 2)
void attn_kernel() {
    extern __shared__ unsigned sm[];
    unsigned* Qs = sm + AQS_O;
    unsigned* Ks = sm + AKS_O;
    unsigned* Vs = sm + AVS_O;
    unsigned* Pt = sm + APT_O;

    const int tid  = threadIdx.x;
    const int lane = tid & 31;
    const int w    = tid >> 5;          // 0..13
    const int row  = lane >> 2;         // 0..7
    const int col  = lane & 3;          // 0..3
    const int b    = blockIdx.x >> 3;
    const int h    = blockIdx.x & 7;
    const int n0   = w * 16;

    // stage Q,K from d-pair layout (coalesced 4B loads)
    const unsigned* __restrict__ qsrc = g_qkP + ((size_t)b * 512 + h * 32) * NPAD;
    const unsigned* __restrict__ ksrc = g_qkP + ((size_t)b * 512 + 256 + h * 32) * NPAD;
    for (int i = tid; i < 32 * NPAD; i += 448) {
        int dp = i / NPAD, m = i - dp * NPAD;
        Qs[dp * KP2 + m] = qsrc[(size_t)dp * NPAD + m];
        Ks[dp * KP2 + m] = ksrc[(size_t)dp * NPAD + m];
    }
    // stage V^T [mp][d] (4B loads along n)
    const unsigned short* __restrict__ vsrc = g_vh + ((size_t)b * 512 + h * 64) * NPAD;
    for (int i = tid; i < 64 * 112; i += 448) {
        int d = i / 112, mp = i - d * 112;
        Vs[mp * VP2 + d] = *(const unsigned*)(vsrc + (size_t)d * NPAD + 2 * mp);
    }
    __syncthreads();

    const float* __restrict__ bptr = g_biasT + (size_t)h * NQ * NQ;
    unsigned* ptw = Pt + w * 16 * PP2;
    const int nb_lo = min(n0 + row, NQ - 1);
    const int nb_hi = min(n0 + row + 8, NQ - 1);

    float o[8][4];
#pragma unroll
    for (int i = 0; i < 8; i++)
#pragma unroll
        for (int j = 0; j < 4; j++) o[i][j] = 0.f;
    float ll = 0.f, lh = 0.f;

    for (int mc = 0; mc < 7; mc++) {
        const int m0 = mc * 32;

        // ---- S = Q^T K for columns [m0, m0+32): 4 k16-steps over d ----
        float c[4][4];
#pragma unroll
        for (int s = 0; s < 4; s++)
#pragma unroll
            for (int j = 0; j < 4; j++) c[s][j] = 0.f;

#pragma unroll
        for (int t = 0; t < 4; t++) {
            const int qb = (t * 8 + col) * KP2 + n0 + row;
            unsigned a[4];
            a[0] = Qs[qb];
            a[1] = Qs[qb + 8];
            a[2] = Qs[qb + 4 * KP2];
            a[3] = Qs[qb + 4 * KP2 + 8];
#pragma unroll
            for (int s = 0; s < 4; s++) {
                const int kb = (t * 8 + col) * KP2 + m0 + s * 8 + row;
                mma_f16(c[s], a, Ks[kb], Ks[kb + 4 * KP2]);
            }
        }

        // exp + bias -> Pt (half2 pairs along m)
#pragma unroll
        for (int s = 0; s < 4; s++) {
            const int m_b = m0 + s * 8 + 2 * col;
            float p0 = 0.f, p1 = 0.f, p2 = 0.f, p3 = 0.f;
            if (m_b < NQ) {
                float2 blo = *(const float2*)(bptr + (size_t)nb_lo * NQ + m_b);
                float2 bhi = *(const float2*)(bptr + (size_t)nb_hi * NQ + m_b);
                p0 = __expf(c[s][0] * 0.125f + blo.x);
                p1 = __expf(c[s][1] * 0.125f + blo.y);
                p2 = __expf(c[s][2] * 0.125f + bhi.x);
                p3 = __expf(c[s][3] * 0.125f + bhi.y);
            }
            ll += p0 + p1;
            lh += p2 + p3;
            ptw[row * PP2 + s * 4 + col]       = packh2(p0, p1);
            ptw[(row + 8) * PP2 + s * 4 + col] = packh2(p2, p3);
        }
        __syncwarp();

        // ---- O += P V^T: 2 k16-steps over this m-chunk ----
#pragma unroll
        for (int u = 0; u < 2; u++) {
            unsigned a[4];
            a[0] = ptw[row * PP2 + u * 8 + col];
            a[1] = ptw[(row + 8) * PP2 + u * 8 + col];
            a[2] = ptw[row * PP2 + u * 8 + col + 4];
            a[3] = ptw[(row + 8) * PP2 + u * 8 + col + 4];
#pragma unroll
            for (int nc = 0; nc < 8; nc++) {
                const int vb = (mc * 16 + u * 8 + col) * VP2 + nc * 8 + row;
                mma_f16(o[nc], a, Vs[vb], Vs[vb + 4 * VP2]);
            }
        }
        __syncwarp();
    }

    // row sums across the quad
    ll += __shfl_xor_sync(0xffffffffu, ll, 1);
    ll += __shfl_xor_sync(0xffffffffu, ll, 2);
    lh += __shfl_xor_sync(0xffffffffu, lh, 1);
    lh += __shfl_xor_sync(0xffffffffu, lh, 2);
    const float linv_lo = 1.f / ll;
    const float linv_hi = 1.f / lh;

    __half* ap = (__half*)g_att;
    const int n_lo = n0 + row;
    const int n_hi = n0 + row + 8;
#pragma unroll
    for (int nc = 0; nc < 8; nc++) {
        int d0 = nc * 8 + 2 * col;
#pragma unroll
        for (int j = 0; j < 2; j++) {
            int d = d0 + j;
            if (n_lo < NQ) {
                float v = o[nc][j] * linv_lo;
                float gl = 0.5f * v * (1.f + erff(v * 0.70710678118654752f));
                int flat = h * (NQ * HD) + n_lo * HD + d;
                int cc   = flat / NQ;
                int pos  = flat - cc * NQ;
                int kp   = cc >> 1;
                int sb   = (kp >> 3) * 4 + (kp & 3);
                int hi   = (kp >> 2) & 1;
                ap[(((size_t)b * 128 + sb) * NPAD + pos) * 4 + hi * 2 + (cc & 1)]
                    = __float2half_rn(gl);
            }
            if (n_hi < NQ) {
                float v = o[nc][j + 2] * linv_hi;
                float gl = 0.5f * v * (1.f + erff(v * 0.70710678118654752f));
                int flat = h * (NQ * HD) + n_hi * HD + d;
                int cc   = flat / NQ;
                int pos  = flat - cc * NQ;
                int kp   = cc >> 1;
                int sb   = (kp >> 3) * 4 + (kp & 3);
                int hi   = (kp >> 2) & 1;
                ap[(((size_t)b * 128 + sb) * NPAD + pos) * 4 + hi * 2 + (cc & 1)]
                    = __float2half_rn(gl);
            }
        }
    }
}

// ---------------------------------------------------------------------------
extern "C" void kernel_launch(void* const* d_in, const int* in_sizes, int n_in,
                              void* d_out, int out_size) {
    const float* x      = (const float*)d_in[0];
    const float* qkv_w  = (const float*)d_in[1];
    const float* bn1_g  = (const float*)d_in[2];
    const float* bn1_b  = (const float*)d_in[3];
    const float* bn1_m  = (const float*)d_in[4];
    const float* bn1_v  = (const float*)d_in[5];
    const float* proj_w = (const float*)d_in[6];
    const float* bn2_g  = (const float*)d_in[7];
    const float* bn2_b  = (const float*)d_in[8];
    const float* bn2_m  = (const float*)d_in[9];
    const float* bn2_v  = (const float*)d_in[10];
    const float* ab     = (const float*)d_in[11];
    const int*   idxs   = (const int*)d_in[12];
    float* out = (float*)d_out;

    const int smem_gemm = (2 * WS_T2 + 2 * XS_T2) * 8;   // 66560 B
    const int smem_attn = ASM_WORDS * 4;                 // 109568 B
    cudaFuncSetAttribute(gemm_f16<0>,
                         cudaFuncAttributeMaxDynamicSharedMemorySize, smem_gemm);
    cudaFuncSetAttribute(gemm_f16<1>,
                         cudaFuncAttributeMaxDynamicSharedMemorySize, smem_gemm);
    cudaFuncSetAttribute(attn_kernel,
                         cudaFuncAttributeMaxDynamicSharedMemorySize, smem_attn);

    {   // convert weights to fp16 pair layout
        int total = 4 * CIN * CIN;
        cvt_w_kernel<<<(total + 255) / 256, 256>>>(qkv_w, proj_w);
    }
    {   // pad + convert x to fp16 pair layout (coalesced)
        int total = B_ * 128 * NPAD * 2;
        pad_cvt_x_kernel<<<(total + 255) / 256, 256>>>(x);
    }
    {   // bias gather
        int total = HEADS * NQ * NQ;
        gather_bias_kernel<<<(total + 255) / 256, 256>>>(ab, idxs);
    }
    {   // QKV GEMM + BN1 -> g_qkP (Q,K pairs) / g_vh (V rows)
        dim3 grid(NPAD / 112, (3 * CIN) / 128, B_);
        gemm_f16<0><<<grid, 256, smem_gemm>>>(bn1_g, bn1_b, bn1_m, bn1_v, nullptr);
    }
    {   // attention + gelu + scrambled reshape
        attn_kernel<<<B_ * HEADS, 448, smem_attn>>>();
    }
    {   // proj GEMM + BN2 -> d_out
        dim3 grid(NPAD / 112, CIN / 128, B_);
        gemm_f16<1><<<grid, 256, smem_gemm>>>(bn2_g, bn2_b, bn2_m, bn2_v, out);
    }
}

// round 14
// speedup vs baseline: 1.0268x; 1.0103x over previous
#include <cuda_runtime.h>
#include <cuda_fp16.h>
#include <math.h>

// ---------------------------------------------------------------------------
// GlobalMHSAWithPosBias: B=128, C=512, RES=14 (N=196), HEADS=8, hd=64
// Round 14 (= round 13 resubmitted; previous run was an infra failure):
// attn mainloop software-pipelined (S(mc+1) -> PV(mc) -> exp(mc+1)) to pull
// bias-load + exp latency off the S->PV critical path; gemm<1> back to
// 2-block reg cap + float2 epilogue stores. gemm<0> = round-12 (measured).
// NOTE: never pass __device__ symbols from host code (rounds-3/4 bug).
// ---------------------------------------------------------------------------

#define B_    128
#define CIN   512
#define NQ    196
#define NPAD  224          // 4 * 56 = 2 * 112
#define HEADS 8
#define HD    64
#define EPS_  1e-5f

// fp16 operand layouts:
//  g_wh: uint2[pr][256 kp], pr = base + (o>>4)*8 + (o&7); .x=h2 W[o], .y=h2 W[o+8]
//  g_xh/g_att: half2 pairs, idx = ((b*128+sb)*224+n)*2 + hi,
//    sb=(kp>>3)*4+(kp&3), hi=(kp>>2)&1, halves by (c&1)
//  g_qkP: unsigned[b][512][224]; row c>>1 (c<1024: Q then K), word m = h2(c, c+1)
//  g_vh : half[b][512][224]; row c-1024 (V), halves along n
__device__ unsigned g_wh [(size_t)1024 * 256 * 2];
__device__ unsigned g_xh [(size_t)B_ * 128 * NPAD * 2];     // BSS 0 (pad cols)
__device__ unsigned g_att[(size_t)B_ * 128 * NPAD * 2];     // BSS 0
__device__ unsigned g_qkP[(size_t)B_ * 512 * NPAD];
__device__ unsigned short g_vh[(size_t)B_ * 512 * NPAD];
__device__ float    g_biasT[HEADS * NQ * NQ];

// ---------------------------------------------------------------------------
__device__ __forceinline__ void mma_f16(float c[4], const unsigned a[4],
                                        unsigned b0, unsigned b1) {
    asm volatile(
        "mma.sync.aligned.m16n8k16.row.col.f32.f16.f16.f32 "
        "{%0,%1,%2,%3}, {%4,%5,%6,%7}, {%8,%9}, {%0,%1,%2,%3};\n"
        : "+f"(c[0]), "+f"(c[1]), "+f"(c[2]), "+f"(c[3])
        : "r"(a[0]), "r"(a[1]), "r"(a[2]), "r"(a[3]), "r"(b0), "r"(b1));
}

__device__ __forceinline__ void cp16(void* dst, const void* src) {
    unsigned s = (unsigned)__cvta_generic_to_shared(dst);
    asm volatile("cp.async.cg.shared.global [%0], [%1], 16;" :: "r"(s), "l"(src));
}
__device__ __forceinline__ void cp_commit() {
    asm volatile("cp.async.commit_group;");
}
template <int N>
__device__ __forceinline__ void cp_wait() {
    asm volatile("cp.async.wait_group %0;" :: "n"(N));
}

__device__ __forceinline__ unsigned packh2(float lo, float hi) {
    __half2 h = __floats2half2_rn(lo, hi);
    return *(unsigned*)&h;
}

// ---------------------------------------------------------------------------
// prologue converters
// ---------------------------------------------------------------------------
__global__ void cvt_w_kernel(const float* __restrict__ qkv_w,
                             const float* __restrict__ proj_w) {
    int i = blockIdx.x * blockDim.x + threadIdx.x;
    const int n1 = 3 * CIN * CIN, total = n1 + CIN * CIN;
    if (i >= total) return;
    float v;
    int o, k, basepr;
    if (i < n1) { v = qkv_w[i];       o = i / CIN;        k = i % CIN;        basepr = 0; }
    else        { v = proj_w[i - n1]; o = (i - n1) / CIN; k = (i - n1) % CIN; basepr = 768; }
    int pr   = basepr + (o >> 4) * 8 + (o & 7);
    int comp = (o >> 3) & 1;
    int kp   = k >> 1;
    ((__half*)g_wh)[(size_t)pr * 1024 + kp * 4 + comp * 2 + (k & 1)]
        = __float2half_rn(v);
}

__global__ void pad_cvt_x_kernel(const float* __restrict__ x) {
    int i = blockIdx.x * blockDim.x + threadIdx.x;
    const int total = B_ * 128 * NPAD * 2;
    if (i >= total) return;
    int hi = i & 1;
    int n  = (i >> 1) % NPAD;
    int r  = (i >> 1) / NPAD;          // b*128 + sb
    if (n >= NQ) return;               // pad cols stay 0 (BSS)
    int b  = r >> 7, sb = r & 127;
    int kp = (sb >> 2) * 8 + hi * 4 + (sb & 3);
    int c  = kp * 2;
    const float* xp = x + ((size_t)b * CIN + c) * NQ + n;
    g_xh[((size_t)r * NPAD + n) * 2 + hi] = packh2(xp[0], xp[NQ]);
}

__global__ void gather_bias_kernel(const float* __restrict__ ab,
                                   const int*   __restrict__ idxs) {
    int i = blockIdx.x * blockDim.x + threadIdx.x;
    const int total = HEADS * NQ * NQ;
    if (i >= total) return;
    int stride = (idxs[1] == 0 && idxs[3] == 0) ? 2 : 1;   // int64 detection
    int h = i / (NQ * NQ);
    int j = i - h * (NQ * NQ);
    g_biasT[i] = ab[h * NQ + idxs[(size_t)j * stride]];
}

// ---------------------------------------------------------------------------
// fp16 GEMM + fused BN affine; pair-packed operands, 2-stage cp.async, BK=64.
// MODE 0: X=g_xh,  W pr base 0,   Y = g_qkP (o<1024, shfl pair-pack) / g_vh
//         launch_bounds(256,3): reg cap 85 -> 3 blocks/SM (measured win)
// MODE 1: X=g_att, W pr base 768, Y = outp (f32, float2 stores, guarded)
//         launch_bounds(256,2): looser regs for the f32 epilogue
// BM=128, BN=112, BK=64, 256 threads (8 warps, 4m x 2n), warp tile 32x56.
// ---------------------------------------------------------------------------
#define WP2 36
#define XP2 116
#define WS_T2 (64 * WP2)
#define XS_T2 (16 * XP2)

template <int MODE>
__global__ __launch_bounds__(256, MODE == 0 ? 3 : 2)
void gemm_f16(const float* __restrict__ gamma, const float* __restrict__ beta,
              const float* __restrict__ mean,  const float* __restrict__ var,
              float* __restrict__ outp) {
    extern __shared__ uint2 smg[];
    uint2* Ws = smg;                  // 2 stages
    uint2* Xs = smg + 2 * WS_T2;      // 2 stages

    const uint2* __restrict__ X2 = (MODE == 0) ? (const uint2*)g_xh
                                               : (const uint2*)g_att;
    const uint2* __restrict__ W2 = (const uint2*)g_wh
                                   + (MODE == 0 ? 0 : (size_t)768 * 256);
    const int Ocnt = (MODE == 0) ? 3 * CIN : CIN;

    const int tid  = threadIdx.x;
    const int lane = tid & 31;
    const int wid  = tid >> 5;
    const int wm   = wid & 3;
    const int n0w  = (wid >> 2) * 56;

    const int b  = blockIdx.z;
    const int o0 = blockIdx.y * 128;
    const int n0 = blockIdx.x * 112;

    const uint2* __restrict__ Wp = W2 + (size_t)(o0 / 2) * 256;
    const uint2* __restrict__ Xp = X2 + ((size_t)b * 128) * NPAD + n0;

    float acc[2][7][4];
#pragma unroll
    for (int i = 0; i < 2; i++)
#pragma unroll
        for (int j = 0; j < 7; j++)
#pragma unroll
            for (int k = 0; k < 4; k++) acc[i][j][k] = 0.f;

    const int row = lane >> 2;
    const int col = lane & 3;

    auto load_tiles = [&](int it, int st) {
        uint2* ws = Ws + st * WS_T2;
        uint2* xs = Xs + st * XS_T2;
#pragma unroll
        for (int i = tid; i < 1024; i += 256) {
            int r = i >> 4, c2 = (i & 15) * 2;
            cp16(ws + r * WP2 + c2, Wp + (size_t)r * 256 + it * 32 + c2);
        }
#pragma unroll
        for (int i = tid; i < 896; i += 256) {
            int r = i / 56, c2 = (i % 56) * 2;
            cp16(xs + r * XP2 + c2, Xp + (size_t)(it * 16 + r) * NPAD + c2);
        }
        cp_commit();
    };

    load_tiles(0, 0);

    for (int it = 0; it < 8; ++it) {
        const int cur = it & 1;
        if (it + 1 < 8) {
            load_tiles(it + 1, (it + 1) & 1);
            cp_wait<1>();
        } else {
            cp_wait<0>();
        }
        __syncthreads();

        const uint2* ws = Ws + cur * WS_T2;
        const uint2* xs = Xs + cur * XS_T2;
#pragma unroll
        for (int ks = 0; ks < 4; ks++) {
            unsigned a[2][4];
#pragma unroll
            for (int mt = 0; mt < 2; mt++) {
                int pr = (wm * 2 + mt) * 8 + row;
                uint2 A01 = ws[pr * WP2 + ks * 8 + col];
                uint2 A23 = ws[pr * WP2 + ks * 8 + col + 4];
                a[mt][0] = A01.x; a[mt][1] = A01.y;
                a[mt][2] = A23.x; a[mt][3] = A23.y;
            }
#pragma unroll
            for (int nt = 0; nt < 7; nt++) {
                uint2 Bf = xs[(ks * 4 + col) * XP2 + n0w + nt * 8 + row];
                mma_f16(acc[0][nt], a[0], Bf.x, Bf.y);
                mma_f16(acc[1][nt], a[1], Bf.x, Bf.y);
            }
        }
        __syncthreads();
    }

    // epilogue: BN affine + store
    const bool qk = (MODE == 0) && (o0 < 1024);
#pragma unroll
    for (int mt = 0; mt < 2; mt++) {
        int o_a = o0 + wm * 32 + mt * 16 + row;
        int o_b = o_a + 8;
        float inv_a = gamma[o_a] * rsqrtf(var[o_a] + EPS_);
        float sh_a  = beta[o_a] - mean[o_a] * inv_a;
        float inv_b = gamma[o_b] * rsqrtf(var[o_b] + EPS_);
        float sh_b  = beta[o_b] - mean[o_b] * inv_b;
#pragma unroll
        for (int nt = 0; nt < 7; nt++) {
            int c0 = n0 + n0w + nt * 8 + col * 2;
            float y0 = acc[mt][nt][0] * inv_a + sh_a;
            float y1 = acc[mt][nt][1] * inv_a + sh_a;
            float y2 = acc[mt][nt][2] * inv_b + sh_b;
            float y3 = acc[mt][nt][3] * inv_b + sh_b;
            if (MODE == 0) {
                if (qk) {
                    // pair channel o with o+1 (held by lane+4: row+1)
                    float z0 = __shfl_down_sync(0xffffffffu, y0, 4);
                    float z1 = __shfl_down_sync(0xffffffffu, y1, 4);
                    float z2 = __shfl_down_sync(0xffffffffu, y2, 4);
                    float z3 = __shfl_down_sync(0xffffffffu, y3, 4);
                    if (!(row & 1)) {
                        int prA = o_a >> 1;               // [0,512)
                        int prB = prA + 4;
                        uint2 wa = make_uint2(packh2(y0, z0), packh2(y1, z1));
                        uint2 wb = make_uint2(packh2(y2, z2), packh2(y3, z3));
                        *(uint2*)(g_qkP + ((size_t)b * 512 + prA) * NPAD + c0) = wa;
                        *(uint2*)(g_qkP + ((size_t)b * 512 + prB) * NPAD + c0) = wb;
                    }
                } else {
                    int ca = o_a - 1024, cb = o_b - 1024;
                    *(unsigned*)(g_vh + ((size_t)b * 512 + ca) * NPAD + c0)
                        = packh2(y0, y1);
                    *(unsigned*)(g_vh + ((size_t)b * 512 + cb) * NPAD + c0)
                        = packh2(y2, y3);
                }
            } else {
                // NQ even & c0 even -> c0<NQ implies c0+1<NQ
                if (c0 < NQ) {
                    float* ya = outp + ((size_t)b * Ocnt + o_a) * NQ;
                    float* yb = outp + ((size_t)b * Ocnt + o_b) * NQ;
                    *(float2*)(ya + c0) = make_float2(y0, y1);
                    *(float2*)(yb + c0) = make_float2(y2, y3);
                }
            }
        }
    }
}

// ---------------------------------------------------------------------------
// fp16 tensor-core attention, software-pipelined mainloop:
//   S(0); exp(0);
//   for mc: [ S(mc+1) ] -> PV(mc) -> syncwarp -> [ exp(mc+1) -> syncwarp ]
// S(mc+1) is independent of Pt(mc), so the bias-LDG + MUFU exp latency
// overlaps the tensor work instead of serializing between S and PV.
// One block per (b,h): 448 threads = 14 warps, 2 blocks/SM.
// ---------------------------------------------------------------------------
#define KP2 232
#define VP2 72
#define PP2 20
#define AQS_O 0
#define AKS_O (32 * KP2)
#define AVS_O (2 * 32 * KP2)
#define APT_O (AVS_O + 112 * VP2)
#define ASM_WORDS (APT_O + 14 * 16 * PP2)

__global__ __launch_bounds__(448, 2)
void attn_kernel() {
    extern __shared__ unsigned sm[];
    unsigned* Qs = sm + AQS_O;
    unsigned* Ks = sm + AKS_O;
    unsigned* Vs = sm + AVS_O;
    unsigned* Pt = sm + APT_O;

    const int tid  = threadIdx.x;
    const int lane = tid & 31;
    const int w    = tid >> 5;          // 0..13
    const int row  = lane >> 2;         // 0..7
    const int col  = lane & 3;          // 0..3
    const int b    = blockIdx.x >> 3;
    const int h    = blockIdx.x & 7;
    const int n0   = w * 16;

    // stage Q,K from d-pair layout (coalesced 4B loads)
    const unsigned* __restrict__ qsrc = g_qkP + ((size_t)b * 512 + h * 32) * NPAD;
    const unsigned* __restrict__ ksrc = g_qkP + ((size_t)b * 512 + 256 + h * 32) * NPAD;
    for (int i = tid; i < 32 * NPAD; i += 448) {
        int dp = i / NPAD, m = i - dp * NPAD;
        Qs[dp * KP2 + m] = qsrc[(size_t)dp * NPAD + m];
        Ks[dp * KP2 + m] = ksrc[(size_t)dp * NPAD + m];
    }
    // stage V^T [mp][d] (4B loads along n)
    const unsigned short* __restrict__ vsrc = g_vh + ((size_t)b * 512 + h * 64) * NPAD;
    for (int i = tid; i < 64 * 112; i += 448) {
        int d = i / 112, mp = i - d * 112;
        Vs[mp * VP2 + d] = *(const unsigned*)(vsrc + (size_t)d * NPAD + 2 * mp);
    }
    __syncthreads();

    const float* __restrict__ bptr = g_biasT + (size_t)h * NQ * NQ;
    unsigned* ptw = Pt + w * 16 * PP2;
    const int nb_lo = min(n0 + row, NQ - 1);
    const int nb_hi = min(n0 + row + 8, NQ - 1);

    float o[8][4];
#pragma unroll
    for (int i = 0; i < 8; i++)
#pragma unroll
        for (int j = 0; j < 4; j++) o[i][j] = 0.f;
    float ll = 0.f, lh = 0.f;

    float c[4][4];

    auto do_S = [&](int mc) {
        const int m0 = mc * 32;
#pragma unroll
        for (int s = 0; s < 4; s++)
#pragma unroll
            for (int j = 0; j < 4; j++) c[s][j] = 0.f;
#pragma unroll
        for (int t = 0; t < 4; t++) {
            const int qb = (t * 8 + col) * KP2 + n0 + row;
            unsigned a[4];
            a[0] = Qs[qb];
            a[1] = Qs[qb + 8];
            a[2] = Qs[qb + 4 * KP2];
            a[3] = Qs[qb + 4 * KP2 + 8];
#pragma unroll
            for (int s = 0; s < 4; s++) {
                const int kb = (t * 8 + col) * KP2 + m0 + s * 8 + row;
                mma_f16(c[s], a, Ks[kb], Ks[kb + 4 * KP2]);
            }
        }
    };

    auto do_exp = [&](int mc) {
        const int m0 = mc * 32;
#pragma unroll
        for (int s = 0; s < 4; s++) {
            const int m_b = m0 + s * 8 + 2 * col;
            float p0 = 0.f, p1 = 0.f, p2 = 0.f, p3 = 0.f;
            if (m_b < NQ) {
                float2 blo = *(const float2*)(bptr + (size_t)nb_lo * NQ + m_b);
                float2 bhi = *(const float2*)(bptr + (size_t)nb_hi * NQ + m_b);
                p0 = __expf(c[s][0] * 0.125f + blo.x);
                p1 = __expf(c[s][1] * 0.125f + blo.y);
                p2 = __expf(c[s][2] * 0.125f + bhi.x);
                p3 = __expf(c[s][3] * 0.125f + bhi.y);
            }
            ll += p0 + p1;
            lh += p2 + p3;
            ptw[row * PP2 + s * 4 + col]       = packh2(p0, p1);
            ptw[(row + 8) * PP2 + s * 4 + col] = packh2(p2, p3);
        }
    };

    auto do_PV = [&](int mc) {
#pragma unroll
        for (int u = 0; u < 2; u++) {
            unsigned a[4];
            a[0] = ptw[row * PP2 + u * 8 + col];
            a[1] = ptw[(row + 8) * PP2 + u * 8 + col];
            a[2] = ptw[row * PP2 + u * 8 + col + 4];
            a[3] = ptw[(row + 8) * PP2 + u * 8 + col + 4];
#pragma unroll
            for (int nc = 0; nc < 8; nc++) {
                const int vb = (mc * 16 + u * 8 + col) * VP2 + nc * 8 + row;
                mma_f16(o[nc], a, Vs[vb], Vs[vb + 4 * VP2]);
            }
        }
    };

    // pipelined mainloop
    do_S(0);
    do_exp(0);
    __syncwarp();
    for (int mc = 0; mc < 7; mc++) {
        if (mc < 6) do_S(mc + 1);       // independent of Pt(mc)
        do_PV(mc);
        __syncwarp();
        if (mc < 6) {
            do_exp(mc + 1);
            __syncwarp();
        }
    }

    // row sums across the quad
    ll += __shfl_xor_sync(0xffffffffu, ll, 1);
    ll += __shfl_xor_sync(0xffffffffu, ll, 2);
    lh += __shfl_xor_sync(0xffffffffu, lh, 1);
    lh += __shfl_xor_sync(0xffffffffu, lh, 2);
    const float linv_lo = 1.f / ll;
    const float linv_hi = 1.f / lh;

    __half* ap = (__half*)g_att;
    const int n_lo = n0 + row;
    const int n_hi = n0 + row + 8;
#pragma unroll
    for (int nc = 0; nc < 8; nc++) {
        int d0 = nc * 8 + 2 * col;
#pragma unroll
        for (int j = 0; j < 2; j++) {
            int d = d0 + j;
            if (n_lo < NQ) {
                float v = o[nc][j] * linv_lo;
                float gl = 0.5f * v * (1.f + erff(v * 0.70710678118654752f));
                int flat = h * (NQ * HD) + n_lo * HD + d;
                int cc   = flat / NQ;
                int pos  = flat - cc * NQ;
                int kp   = cc >> 1;
                int sb   = (kp >> 3) * 4 + (kp & 3);
                int hi   = (kp >> 2) & 1;
                ap[(((size_t)b * 128 + sb) * NPAD + pos) * 4 + hi * 2 + (cc & 1)]
                    = __float2half_rn(gl);
            }
            if (n_hi < NQ) {
                float v = o[nc][j + 2] * linv_hi;
                float gl = 0.5f * v * (1.f + erff(v * 0.70710678118654752f));
                int flat = h * (NQ * HD) + n_hi * HD + d;
                int cc   = flat / NQ;
                int pos  = flat - cc * NQ;
                int kp   = cc >> 1;
                int sb   = (kp >> 3) * 4 + (kp & 3);
                int hi   = (kp >> 2) & 1;
                ap[(((size_t)b * 128 + sb) * NPAD + pos) * 4 + hi * 2 + (cc & 1)]
                    = __float2half_rn(gl);
            }
        }
    }
}

// ---------------------------------------------------------------------------
extern "C" void kernel_launch(void* const* d_in, const int* in_sizes, int n_in,
                              void* d_out, int out_size) {
    const float* x      = (const float*)d_in[0];
    const float* qkv_w  = (const float*)d_in[1];
    const float* bn1_g  = (const float*)d_in[2];
    const float* bn1_b  = (const float*)d_in[3];
    const float* bn1_m  = (const float*)d_in[4];
    const float* bn1_v  = (const float*)d_in[5];
    const float* proj_w = (const float*)d_in[6];
    const float* bn2_g  = (const float*)d_in[7];
    const float* bn2_b  = (const float*)d_in[8];
    const float* bn2_m  = (const float*)d_in[9];
    const float* bn2_v  = (const float*)d_in[10];
    const float* ab     = (const float*)d_in[11];
    const int*   idxs   = (const int*)d_in[12];
    float* out = (float*)d_out;

    const int smem_gemm = (2 * WS_T2 + 2 * XS_T2) * 8;   // 66560 B
    const int smem_attn = ASM_WORDS * 4;                 // 109568 B
    cudaFuncSetAttribute(gemm_f16<0>,
                         cudaFuncAttributeMaxDynamicSharedMemorySize, smem_gemm);
    cudaFuncSetAttribute(gemm_f16<1>,
                         cudaFuncAttributeMaxDynamicSharedMemorySize, smem_gemm);
    cudaFuncSetAttribute(attn_kernel,
                         cudaFuncAttributeMaxDynamicSharedMemorySize, smem_attn);

    {   // convert weights to fp16 pair layout
        int total = 4 * CIN * CIN;
        cvt_w_kernel<<<(total + 255) / 256, 256>>>(qkv_w, proj_w);
    }
    {   // pad + convert x to fp16 pair layout (coalesced)
        int total = B_ * 128 * NPAD * 2;
        pad_cvt_x_kernel<<<(total + 255) / 256, 256>>>(x);
    }
    {   // bias gather
        int total = HEADS * NQ * NQ;
        gather_bias_kernel<<<(total + 255) / 256, 256>>>(ab, idxs);
    }
    {   // QKV GEMM + BN1 -> g_qkP (Q,K pairs) / g_vh (V rows)
        dim3 grid(NPAD / 112, (3 * CIN) / 128, B_);
        gemm_f16<0><<<grid, 256, smem_gemm>>>(bn1_g, bn1_b, bn1_m, bn1_v, nullptr);
    }
    {   // attention + gelu + scrambled reshape (pipelined)
        attn_kernel<<<B_ * HEADS, 448, smem_attn>>>();
    }
    {   // proj GEMM + BN2 -> d_out
        dim3 grid(NPAD / 112, CIN / 128, B_);
        gemm_f16<1><<<grid, 256, smem_gemm>>>(bn2_g, bn2_b, bn2_m, bn2_v, out);
    }
}